// round 2
// baseline (speedup 1.0000x reference)
#include <cuda_runtime.h>
#include <cuda_bf16.h>
#include <cstdint>

#define NN 2048
#define BB 64
#define TT 512
#define CTAS 128
#define THREADS 256
#define PITCHB 4112                        // 2048*2 + 16 bytes, conflict-free rows

// ---- shared memory layout (bytes from dynamic smem base) ----
#define OFF_WHI 0
#define OFF_WLO (16 * PITCHB)              // 65792
#define OFF_SPK (32 * PITCHB)              // 131584
#define SPK_STRIDE 68                      // u32 words per spike row (padded)
#define OFF_MEM (OFF_SPK + 64 * SPK_STRIDE * 4)   // 148992
#define OFF_RED (OFF_MEM + 64 * 18 * 4)           // 153600
#define SMEM_TOTAL (OFF_RED + 4096)               // 157696

// ---- persistent device state ----
__device__ __align__(16) __nv_bfloat16 g_Whi[NN * NN];   // [n][k] = 0.1*eff^T, hi
__device__ __align__(16) __nv_bfloat16 g_Wlo[NN * NN];   // residual
__device__ __align__(16) uint32_t g_spk0[BB * (NN / 32)]; // packed spikes, parity 0
__device__ __align__(16) uint32_t g_spk1[BB * (NN / 32)]; // parity 1
__device__ uint32_t g_bar;

// ---- helpers ----
__device__ __forceinline__ uint32_t smem_u32(const void* p) {
    uint32_t a;
    asm("{ .reg .u64 t; cvta.to.shared.u64 t, %1; cvt.u32.u64 %0, t; }" : "=r"(a) : "l"(p));
    return a;
}

__device__ __forceinline__ void ldsm4(uint32_t* r, uint32_t addr) {
    asm volatile("ldmatrix.sync.aligned.m8n8.x4.shared.b16 {%0,%1,%2,%3}, [%4];"
                 : "=r"(r[0]), "=r"(r[1]), "=r"(r[2]), "=r"(r[3]) : "r"(addr));
}

__device__ __forceinline__ void mma_bf16(float* c, const uint32_t* a, uint32_t b0, uint32_t b1) {
    asm volatile(
        "mma.sync.aligned.m16n8k16.row.col.f32.bf16.bf16.f32 "
        "{%0,%1,%2,%3},{%4,%5,%6,%7},{%8,%9},{%0,%1,%2,%3};"
        : "+f"(c[0]), "+f"(c[1]), "+f"(c[2]), "+f"(c[3])
        : "r"(a[0]), "r"(a[1]), "r"(a[2]), "r"(a[3]), "r"(b0), "r"(b1));
}

// two spike bits (sh, sh+1) -> packed bf16x2 {1.0|0.0, 1.0|0.0}
__device__ __forceinline__ uint32_t bits2bf(uint32_t w, int sh) {
    uint32_t t = w >> sh;
    return ((t & 1u) ? 0x00003F80u : 0u) | ((t & 2u) ? 0x3F800000u : 0u);
}

// ---- weight prep: transpose + zero diag + 0.1 scale + bf16 hi/lo split ----
__global__ void conv_kernel(const float* __restrict__ rec) {
    __shared__ float tile[32][33];
    int k = blockIdx.y * 32 + threadIdx.y;
    int n = blockIdx.x * 32 + threadIdx.x;
    tile[threadIdx.y][threadIdx.x] = rec[k * NN + n];
    __syncthreads();
    int nn = blockIdx.x * 32 + threadIdx.y;
    int kk = blockIdx.y * 32 + threadIdx.x;
    float w = tile[threadIdx.x][threadIdx.y];          // rec[kk][nn]
    float v = (nn == kk) ? 0.0f : 0.1f * w;
    __nv_bfloat16 hi = __float2bfloat16(v);
    float resid = v - __bfloat162float(hi);
    g_Whi[nn * NN + kk] = hi;
    g_Wlo[nn * NN + kk] = __float2bfloat16(resid);
}

__global__ void init_kernel() {
    int i = blockIdx.x * blockDim.x + threadIdx.x;
    if (i < BB * (NN / 32)) { g_spk0[i] = 0u; g_spk1[i] = 0u; }
    if (i == 0) g_bar = 0u;
}

// ---- persistent RSNN kernel: 128 CTAs, one per 16-neuron slice ----
__global__ void __launch_bounds__(THREADS, 1)
rsnn_kernel(const float* __restrict__ x, float* __restrict__ out) {
    extern __shared__ char smem[];
    const uint32_t sbase = smem_u32(smem);

    const int tid = threadIdx.x;
    const int wid = tid >> 5;
    const int lane = tid & 31;
    const int n0 = blockIdx.x * 16;

    // ---- load this CTA's weight slice into SMEM once (hi + lo, pitched) ----
    for (int i = tid; i < 16 * 256; i += THREADS) {      // 256 uint4 per row
        int row = i >> 8, c = i & 255;
        *(uint4*)(smem + OFF_WHI + row * PITCHB + c * 16) =
            *(const uint4*)(g_Whi + (size_t)(n0 + row) * NN + c * 8);
        *(uint4*)(smem + OFF_WLO + row * PITCHB + c * 16) =
            *(const uint4*)(g_Wlo + (size_t)(n0 + row) * NN + c * 8);
    }
    // zero membrane state (lives in SMEM for the whole run)
    for (int i = tid; i < 64 * 18; i += THREADS)
        ((float*)(smem + OFF_MEM))[i] = 0.0f;
    __syncthreads();

    // per-warp constants
    const int m = wid & 3;         // m16 tile (batch group)
    const int kh = wid >> 2;       // k half
    const int b0r = m * 16 + (lane >> 2);
    uint32_t ldsm_off;
    {
        int grp = lane >> 3;                       // which 8x8 matrix
        int row = ((grp >> 1) << 3) + (lane & 7);  // local neuron row
        int koff = (grp & 1) * 8;                  // k offset within k16
        ldsm_off = row * PITCHB + koff * 2;
    }
    const int c0 = (lane & 3) * 2;
    const int wsel = (n0 >> 5);
    const int bitbase = (n0 & 31) + c0;
    uint32_t* const spkS = (uint32_t*)(smem + OFF_SPK);
    float* const memS = (float*)(smem + OFF_MEM);
    float* const redS = (float*)(smem + OFF_RED);

    for (int t = 0; t < TT; ++t) {
        const uint32_t* gsrc = (t & 1) ? g_spk1 : g_spk0;
        uint32_t* gdst = (t & 1) ? g_spk0 : g_spk1;

        // ---- stage packed spikes [64 x 64 u32] -> padded SMEM rows ----
        {
            const uint4* src = (const uint4*)gsrc;
            #pragma unroll
            for (int i = tid; i < 1024; i += THREADS) {
                int row = i >> 4, c4 = i & 15;
                uint4 v = __ldcg(src + i);
                *(uint4*)(smem + OFF_SPK + (row * SPK_STRIDE + c4 * 4) * 4) = v;
            }
        }
        __syncthreads();

        // ---- GEMM: D[64 x 16] = spk(bits->bf16) @ [Whi + Wlo]^T ----
        float acc0[4] = {0.f, 0.f, 0.f, 0.f};
        float acc1[4] = {0.f, 0.f, 0.f, 0.f};
        #pragma unroll 4
        for (int kt2 = 0; kt2 < 32; ++kt2) {
            const int widx = kh * 32 + kt2;
            const uint32_t w0 = spkS[b0r * SPK_STRIDE + widx];
            const uint32_t w1 = spkS[(b0r + 8) * SPK_STRIDE + widx];
            #pragma unroll
            for (int h = 0; h < 2; ++h) {
                const int kt = widx * 2 + h;
                const int sh = h * 16 + c0;
                uint32_t a[4];
                a[0] = bits2bf(w0, sh);
                a[1] = bits2bf(w1, sh);
                a[2] = bits2bf(w0, sh + 8);
                a[3] = bits2bf(w1, sh + 8);
                uint32_t bh[4], bl[4];
                ldsm4(bh, sbase + OFF_WHI + ldsm_off + kt * 32);
                ldsm4(bl, sbase + OFF_WLO + ldsm_off + kt * 32);
                mma_bf16(acc0, a, bh[0], bh[1]);
                mma_bf16(acc1, a, bh[2], bh[3]);
                mma_bf16(acc0, a, bl[0], bl[1]);
                mma_bf16(acc1, a, bl[2], bl[3]);
            }
        }

        // ---- split-k reduce: warps 4-7 dump partials, warps 0-3 add ----
        if (wid >= 4) {
            float* p = redS + ((wid - 4) * 32 + lane) * 8;
            p[0] = acc0[0]; p[1] = acc0[1]; p[2] = acc0[2]; p[3] = acc0[3];
            p[4] = acc1[0]; p[5] = acc1[1]; p[6] = acc1[2]; p[7] = acc1[3];
        }
        __syncthreads();

        if (wid < 4) {
            const float* p = redS + (wid * 32 + lane) * 8;
            acc0[0] += p[0]; acc0[1] += p[1]; acc0[2] += p[2]; acc0[3] += p[3];
            acc1[0] += p[4]; acc1[1] += p[5]; acc1[2] += p[6]; acc1[3] += p[7];

            // ---- LIF epilogue: 2 rows x 4 cols per thread ----
            #pragma unroll
            for (int ri = 0; ri < 2; ++ri) {
                const int b = b0r + ri * 8;
                const float* xp = x + ((size_t)b * TT + t) * NN + n0 + c0;
                float2 xa = __ldg((const float2*)xp);
                float2 xb = __ldg((const float2*)(xp + 8));
                float* mp = memS + b * 18 + c0;
                float2 ma = *(float2*)mp;
                float2 mb = *(float2*)(mp + 8);
                uint32_t pw = spkS[b * SPK_STRIDE + wsel] >> bitbase;

                float cur0 = xa.x + acc0[ri * 2 + 0];
                float cur1 = xa.y + acc0[ri * 2 + 1];
                float cur2 = xb.x + acc1[ri * 2 + 0];
                float cur3 = xb.y + acc1[ri * 2 + 1];

                float m0 = (pw & 1u) ? cur0 : fmaf(0.96f, ma.x, cur0);
                float m1 = (pw & 2u) ? cur1 : fmaf(0.96f, ma.y, cur1);
                float m2 = ((pw >> 8) & 1u) ? cur2 : fmaf(0.96f, mb.x, cur2);
                float m3 = ((pw >> 8) & 2u) ? cur3 : fmaf(0.96f, mb.y, cur3);

                unsigned s0 = (m0 >= 0.5f), s1 = (m1 >= 0.5f);
                unsigned s2 = (m2 >= 0.5f), s3 = (m3 >= 0.5f);

                *(float2*)mp = make_float2(m0, m1);
                *(float2*)(mp + 8) = make_float2(m2, m3);

                float* op = out + ((size_t)b * TT + t) * NN + n0 + c0;
                *(float2*)op = make_float2((float)s0, (float)s1);
                *(float2*)(op + 8) = make_float2((float)s2, (float)s3);

                unsigned v = (s0 << c0) | (s1 << (c0 + 1)) |
                             (s2 << (c0 + 8)) | (s3 << (c0 + 9));
                v |= __shfl_xor_sync(0xFFFFFFFFu, v, 1);
                v |= __shfl_xor_sync(0xFFFFFFFFu, v, 2);
                if ((lane & 3) == 0)
                    ((uint16_t*)gdst)[b * 128 + blockIdx.x] = (uint16_t)v;
            }
        } else {
            // keep shuffles structurally balanced (no-op for these warps)
        }

        // ---- global step barrier (release/acquire on L2 counter) ----
        __syncthreads();
        if (tid == 0) {
            const unsigned tgt = (unsigned)(CTAS * (t + 1));
            asm volatile("red.release.gpu.global.add.u32 [%0], 1;" :: "l"(&g_bar) : "memory");
            unsigned v;
            do {
                asm volatile("ld.acquire.gpu.global.u32 %0, [%1];" : "=r"(v) : "l"(&g_bar) : "memory");
            } while (v < tgt);
        }
        __syncthreads();
    }
}

// ---- launch ----
extern "C" void kernel_launch(void* const* d_in, const int* in_sizes, int n_in,
                              void* d_out, int out_size) {
    const float* x = (const float*)d_in[0];
    const float* rec = (const float*)d_in[1];
    if (n_in >= 2 && in_sizes[0] == NN * NN) {   // robustness to ordering
        x = (const float*)d_in[1];
        rec = (const float*)d_in[0];
    }
    float* out = (float*)d_out;

    cudaFuncSetAttribute(rsnn_kernel, cudaFuncAttributeMaxDynamicSharedMemorySize, SMEM_TOTAL);

    dim3 cg(NN / 32, NN / 32), cb(32, 32);
    conv_kernel<<<cg, cb>>>(rec);
    init_kernel<<<(BB * (NN / 32) + 255) / 256, 256>>>();
    rsnn_kernel<<<CTAS, THREADS, SMEM_TOTAL>>>(x, out);
}

// round 3
// speedup vs baseline: 1.2280x; 1.2280x over previous
#include <cuda_runtime.h>
#include <cuda_bf16.h>
#include <cstdint>

#define NN 2048
#define BB 64
#define TT 512
#define CTAS 128
#define THREADS 256
#define PITCHB 4112                 // 2048*2 + 16 bytes, conflict-free ldmatrix rows

// ---- shared memory layout ----
#define OFF_WHI 0
#define OFF_WLO (16 * PITCHB)               // 65792
#define OFF_SPK (32 * PITCHB)               // 131584
#define SPK_STRIDE 68                       // u32 words per spike row (padded)
#define OFF_MEM (OFF_SPK + 64 * SPK_STRIDE * 4)   // 148992
#define OFF_RED (OFF_MEM + 64 * 16 * 4)           // 153088
#define SMEM_TOTAL (OFF_RED + 8 * 1024 * 4)       // 185856

// ---- persistent device state ----
__device__ __align__(16) __nv_bfloat16 g_Whi[NN * NN];    // [n][k] = 0.1*eff^T, hi
__device__ __align__(16) __nv_bfloat16 g_Wlo[NN * NN];    // residual
__device__ __align__(16) uint32_t g_spk0[BB * (NN / 32)];
__device__ __align__(16) uint32_t g_spk1[BB * (NN / 32)];
__device__ uint32_t g_bar;

// ---- helpers ----
__device__ __forceinline__ uint32_t smem_u32(const void* p) {
    uint32_t a;
    asm("{ .reg .u64 t; cvta.to.shared.u64 t, %1; cvt.u32.u64 %0, t; }" : "=r"(a) : "l"(p));
    return a;
}

__device__ __forceinline__ void ldsm4(uint32_t* r, uint32_t addr) {
    asm volatile("ldmatrix.sync.aligned.m8n8.x4.shared.b16 {%0,%1,%2,%3}, [%4];"
                 : "=r"(r[0]), "=r"(r[1]), "=r"(r[2]), "=r"(r[3]) : "r"(addr));
}

__device__ __forceinline__ void mma_bf16(float* c, const uint32_t* a, uint32_t b0, uint32_t b1) {
    asm volatile(
        "mma.sync.aligned.m16n8k16.row.col.f32.bf16.bf16.f32 "
        "{%0,%1,%2,%3},{%4,%5,%6,%7},{%8,%9},{%0,%1,%2,%3};"
        : "+f"(c[0]), "+f"(c[1]), "+f"(c[2]), "+f"(c[3])
        : "r"(a[0]), "r"(a[1]), "r"(a[2]), "r"(a[3]), "r"(b0), "r"(b1));
}

// two spike bits (sh, sh+1) -> packed bf16x2 {1|0, 1|0}
__device__ __forceinline__ uint32_t bits2bf(uint32_t w, int sh) {
    uint32_t t = w >> sh;
    return ((t & 1u) ? 0x00003F80u : 0u) | ((t & 2u) ? 0x3F800000u : 0u);
}

// ---- prep: transpose + zero diag + 0.1 scale + bf16 hi/lo split, plus state init ----
__global__ void prep_kernel(const float* __restrict__ rec) {
    __shared__ float tile[32][33];
    int k = blockIdx.y * 32 + threadIdx.y;
    int n = blockIdx.x * 32 + threadIdx.x;
    tile[threadIdx.y][threadIdx.x] = rec[k * NN + n];

    // state init folded in (first few blocks)
    int fb = blockIdx.y * gridDim.x + blockIdx.x;
    int ft = threadIdx.y * 32 + threadIdx.x;
    if (fb < 4)      g_spk0[fb * 1024 + ft] = 0u;
    else if (fb < 8) g_spk1[(fb - 4) * 1024 + ft] = 0u;
    else if (fb == 8 && ft == 0) g_bar = 0u;

    __syncthreads();
    int nn = blockIdx.x * 32 + threadIdx.y;
    int kk = blockIdx.y * 32 + threadIdx.x;
    float w = tile[threadIdx.x][threadIdx.y];      // rec[kk][nn]
    float v = (nn == kk) ? 0.0f : 0.1f * w;
    __nv_bfloat16 hi = __float2bfloat16(v);
    float resid = v - __bfloat162float(hi);
    g_Whi[nn * NN + kk] = hi;
    g_Wlo[nn * NN + kk] = __float2bfloat16(resid);
}

// ---- persistent RSNN kernel: 128 CTAs, one per 16-neuron slice ----
__global__ void __launch_bounds__(THREADS, 1)
rsnn_kernel(const float* __restrict__ x, float* __restrict__ out) {
    extern __shared__ char smem[];
    const uint32_t sbase = smem_u32(smem);

    const int tid = threadIdx.x;
    const int wid = tid >> 5;           // warp = k-eighth
    const int lane = tid & 31;
    const int n0 = blockIdx.x * 16;

    // ---- load weight slice into SMEM once (hi + lo, pitched) ----
    for (int i = tid; i < 16 * 256; i += THREADS) {
        int row = i >> 8, c = i & 255;
        *(uint4*)(smem + OFF_WHI + row * PITCHB + c * 16) =
            *(const uint4*)(g_Whi + (size_t)(n0 + row) * NN + c * 8);
        *(uint4*)(smem + OFF_WLO + row * PITCHB + c * 16) =
            *(const uint4*)(g_Wlo + (size_t)(n0 + row) * NN + c * 8);
    }
    for (int i = tid; i < 64 * 16; i += THREADS)
        ((float*)(smem + OFF_MEM))[i] = 0.0f;
    __syncthreads();

    // per-thread constants
    const int rowq = lane >> 2;           // 0..7
    const int c0 = (lane & 3) * 2;        // k column pair base
    uint32_t ldsm_off;
    {
        int grp = lane >> 3;
        int row = ((grp >> 1) << 3) + (lane & 7);
        int koff = (grp & 1) * 8;
        ldsm_off = row * PITCHB + koff * 2;
    }
    const int eb = tid >> 2;              // epilogue batch row 0..63
    const int eq = (tid & 3) * 4;         // epilogue col base 0..12
    const int wsel = n0 >> 5;
    const int bsh = (n0 & 31) + eq;

    uint32_t* const spkS = (uint32_t*)(smem + OFF_SPK);
    float* const memS = (float*)(smem + OFF_MEM);
    float* const redS = (float*)(smem + OFF_RED);

    for (int t = 0; t < TT; ++t) {
        const uint32_t* gsrc = (t & 1) ? g_spk1 : g_spk0;
        uint32_t* gdst = (t & 1) ? g_spk0 : g_spk1;

        // ---- prefetch x for this step (consumed in epilogue; latency hidden by GEMM) ----
        float4 xv = __ldg((const float4*)(x + ((size_t)eb * TT + t) * NN + n0 + eq));

        // ---- stage packed spikes [64 x 64 u32] -> padded SMEM rows ----
        {
            const uint4* src = (const uint4*)gsrc;
            #pragma unroll
            for (int i = tid; i < 1024; i += THREADS) {
                int row = i >> 4, c4 = i & 15;
                uint4 v = __ldcg(src + i);
                *(uint4*)(smem + OFF_SPK + (row * SPK_STRIDE + c4 * 4) * 4) = v;
            }
        }
        __syncthreads();

        // ---- GEMM: each warp owns a k-eighth, all 4 m-tiles, B-stationary per kt ----
        float acc[4][2][4];
        #pragma unroll
        for (int m = 0; m < 4; ++m)
            #pragma unroll
            for (int nh = 0; nh < 2; ++nh)
                #pragma unroll
                for (int e = 0; e < 4; ++e) acc[m][nh][e] = 0.0f;

        #pragma unroll 2
        for (int j = 0; j < 8; ++j) {
            const int widx = (wid << 3) + j;          // u32 spike word index
            uint32_t bh[2][4], bl[2][4];
            #pragma unroll
            for (int h = 0; h < 2; ++h) {
                const int kt = widx * 2 + h;
                ldsm4(bh[h], sbase + OFF_WHI + ldsm_off + kt * 32);
                ldsm4(bl[h], sbase + OFF_WLO + ldsm_off + kt * 32);
            }
            #pragma unroll
            for (int m = 0; m < 4; ++m) {
                const uint32_t w0 = spkS[(m * 16 + rowq) * SPK_STRIDE + widx];
                const uint32_t w1 = spkS[(m * 16 + rowq + 8) * SPK_STRIDE + widx];
                #pragma unroll
                for (int h = 0; h < 2; ++h) {
                    const int sh = h * 16 + c0;
                    uint32_t a[4];
                    a[0] = bits2bf(w0, sh);
                    a[1] = bits2bf(w1, sh);
                    a[2] = bits2bf(w0, sh + 8);
                    a[3] = bits2bf(w1, sh + 8);
                    mma_bf16(acc[m][0], a, bh[h][0], bh[h][1]);
                    mma_bf16(acc[m][1], a, bh[h][2], bh[h][3]);
                    mma_bf16(acc[m][0], a, bl[h][0], bl[h][1]);
                    mma_bf16(acc[m][1], a, bl[h][2], bl[h][3]);
                }
            }
        }

        // ---- dump per-warp partials (each warp has a full 64x16 partial) ----
        {
            float* pw = redS + wid * 1024;
            #pragma unroll
            for (int m = 0; m < 4; ++m)
                #pragma unroll
                for (int nh = 0; nh < 2; ++nh) {
                    const int col = nh * 8 + c0;
                    const int r = m * 16 + rowq;
                    *(float2*)(pw + r * 16 + col) = make_float2(acc[m][nh][0], acc[m][nh][1]);
                    *(float2*)(pw + (r + 8) * 16 + col) = make_float2(acc[m][nh][2], acc[m][nh][3]);
                }
        }
        __syncthreads();

        // ---- reduce 8 partials + LIF epilogue (4 outputs per thread) ----
        float4 s = *(float4*)(redS + eb * 16 + eq);
        #pragma unroll
        for (int w = 1; w < 8; ++w) {
            float4 p = *(float4*)(redS + w * 1024 + eb * 16 + eq);
            s.x += p.x; s.y += p.y; s.z += p.z; s.w += p.w;
        }

        float4 mv = *(float4*)(memS + eb * 16 + eq);
        const uint32_t pw = spkS[eb * SPK_STRIDE + wsel] >> bsh;

        float cur0 = xv.x + s.x, cur1 = xv.y + s.y;
        float cur2 = xv.z + s.z, cur3 = xv.w + s.w;
        float m0 = (pw & 1u) ? cur0 : fmaf(0.96f, mv.x, cur0);
        float m1 = (pw & 2u) ? cur1 : fmaf(0.96f, mv.y, cur1);
        float m2 = (pw & 4u) ? cur2 : fmaf(0.96f, mv.z, cur2);
        float m3 = (pw & 8u) ? cur3 : fmaf(0.96f, mv.w, cur3);

        unsigned s0 = (m0 >= 0.5f), s1 = (m1 >= 0.5f);
        unsigned s2 = (m2 >= 0.5f), s3 = (m3 >= 0.5f);

        *(float4*)(memS + eb * 16 + eq) = make_float4(m0, m1, m2, m3);

        // pack new spike bits -> u16 per (batch row, CTA)
        unsigned v = (s0 | (s1 << 1) | (s2 << 2) | (s3 << 3)) << eq;
        v |= __shfl_xor_sync(0xFFFFFFFFu, v, 1);
        v |= __shfl_xor_sync(0xFFFFFFFFu, v, 2);
        if ((tid & 3) == 0)
            ((uint16_t*)gdst)[eb * 128 + blockIdx.x] = (uint16_t)v;

        // ---- barrier arrive (spikes visible), then overlap out-store with wait ----
        __syncthreads();
        if (tid == 0)
            asm volatile("red.release.gpu.global.add.u32 [%0], 1;" :: "l"(&g_bar) : "memory");

        *(float4*)(out + ((size_t)eb * TT + t) * NN + n0 + eq) =
            make_float4((float)s0, (float)s1, (float)s2, (float)s3);

        if (tid == 0) {
            const unsigned tgt = (unsigned)(CTAS * (t + 1));
            unsigned bv;
            do {
                asm volatile("ld.acquire.gpu.global.u32 %0, [%1];" : "=r"(bv) : "l"(&g_bar) : "memory");
            } while (bv < tgt);
        }
        __syncthreads();
    }
}

// ---- launch ----
extern "C" void kernel_launch(void* const* d_in, const int* in_sizes, int n_in,
                              void* d_out, int out_size) {
    const float* x = (const float*)d_in[0];
    const float* rec = (const float*)d_in[1];
    if (n_in >= 2 && in_sizes[0] == NN * NN) {
        x = (const float*)d_in[1];
        rec = (const float*)d_in[0];
    }
    float* out = (float*)d_out;

    cudaFuncSetAttribute(rsnn_kernel, cudaFuncAttributeMaxDynamicSharedMemorySize, SMEM_TOTAL);

    dim3 cg(NN / 32, NN / 32), cb(32, 32);
    prep_kernel<<<cg, cb>>>(rec);
    rsnn_kernel<<<CTAS, THREADS, SMEM_TOTAL>>>(x, out);
}

// round 4
// speedup vs baseline: 1.4070x; 1.1458x over previous
#include <cuda_runtime.h>
#include <cuda_bf16.h>
#include <cstdint>

#define NN 2048
#define BB 64
#define TT 512
#define CTAS 128
#define THREADS 256
#define PITCHB 4112                 // 2048*2 + 16 bytes, conflict-free ldmatrix rows

// ---- shared memory layout ----
#define OFF_WHI 0
#define OFF_WLO (16 * PITCHB)               // 65792
#define OFF_SPK (32 * PITCHB)               // 131584
#define SPK_STRIDE 68                       // u32 words per spike row (padded)
#define OFF_MEM (OFF_SPK + 64 * SPK_STRIDE * 4)   // 148992
#define OFF_RED (OFF_MEM + 64 * 16 * 4)           // 153088
#define OFF_LUT (OFF_RED + 8 * 1024 * 4)          // 185856
#define SMEM_TOTAL (OFF_LUT + 256)                // 186112

// ---- persistent device state ----
__device__ __align__(16) __nv_bfloat16 g_Whi[NN * NN];    // [n][k] = 0.1*eff^T, hi
__device__ __align__(16) __nv_bfloat16 g_Wlo[NN * NN];    // residual
__device__ __align__(16) uint32_t g_spk0[BB * (NN / 32)]; // bit-permuted packed spikes
__device__ __align__(16) uint32_t g_spk1[BB * (NN / 32)];
__device__ uint32_t g_bar;

// Spike bit permutation: within each 16-bit half (h = k>=16), local c = k&15 sits at
//   np(c) = ((c&7)>>1)*4 + (c&1) + 2*((c>>3)&1)
// so nibble q of a half = bits {k=2q, 2q+1, 2q+8, 2q+9}: exactly one lane's A-pair bits.

// ---- helpers ----
__device__ __forceinline__ uint32_t smem_u32(const void* p) {
    uint32_t a;
    asm("{ .reg .u64 t; cvta.to.shared.u64 t, %1; cvt.u32.u64 %0, t; }" : "=r"(a) : "l"(p));
    return a;
}

__device__ __forceinline__ void ldsm4(uint32_t* r, uint32_t addr) {
    asm volatile("ldmatrix.sync.aligned.m8n8.x4.shared.b16 {%0,%1,%2,%3}, [%4];"
                 : "=r"(r[0]), "=r"(r[1]), "=r"(r[2]), "=r"(r[3]) : "r"(addr));
}

__device__ __forceinline__ void mma_bf16(float* c, const uint32_t* a, uint32_t b0, uint32_t b1) {
    asm volatile(
        "mma.sync.aligned.m16n8k16.row.col.f32.bf16.bf16.f32 "
        "{%0,%1,%2,%3},{%4,%5,%6,%7},{%8,%9},{%0,%1,%2,%3};"
        : "+f"(c[0]), "+f"(c[1]), "+f"(c[2]), "+f"(c[3])
        : "r"(a[0]), "r"(a[1]), "r"(a[2]), "r"(a[3]), "r"(b0), "r"(b1));
}

// ---- prep: transpose + zero diag + 0.1 scale + bf16 hi/lo split, plus state init ----
__global__ void prep_kernel(const float* __restrict__ rec) {
    __shared__ float tile[32][33];
    int k = blockIdx.y * 32 + threadIdx.y;
    int n = blockIdx.x * 32 + threadIdx.x;
    tile[threadIdx.y][threadIdx.x] = rec[k * NN + n];

    int fb = blockIdx.y * gridDim.x + blockIdx.x;
    int ft = threadIdx.y * 32 + threadIdx.x;
    if (fb < 4)      g_spk0[fb * 1024 + ft] = 0u;
    else if (fb < 8) g_spk1[(fb - 4) * 1024 + ft] = 0u;
    else if (fb == 8 && ft == 0) g_bar = 0u;

    __syncthreads();
    int nn = blockIdx.x * 32 + threadIdx.y;
    int kk = blockIdx.y * 32 + threadIdx.x;
    float w = tile[threadIdx.x][threadIdx.y];      // rec[kk][nn]
    float v = (nn == kk) ? 0.0f : 0.1f * w;
    __nv_bfloat16 hi = __float2bfloat16(v);
    float resid = v - __bfloat162float(hi);
    g_Whi[nn * NN + kk] = hi;
    g_Wlo[nn * NN + kk] = __float2bfloat16(resid);
}

// ---- persistent RSNN kernel: 128 CTAs, one per 16-neuron slice ----
__global__ void __launch_bounds__(THREADS, 1)
rsnn_kernel(const float* __restrict__ x, float* __restrict__ out) {
    extern __shared__ char smem[];
    const uint32_t sbase = smem_u32(smem);

    const int tid = threadIdx.x;
    const int wid = tid >> 5;           // warp = k-eighth
    const int lane = tid & 31;
    const int n0 = blockIdx.x * 16;

    // ---- load weight slice into SMEM once (hi + lo, pitched) ----
    for (int i = tid; i < 16 * 256; i += THREADS) {
        int row = i >> 8, c = i & 255;
        *(uint4*)(smem + OFF_WHI + row * PITCHB + c * 16) =
            *(const uint4*)(g_Whi + (size_t)(n0 + row) * NN + c * 8);
        *(uint4*)(smem + OFF_WLO + row * PITCHB + c * 16) =
            *(const uint4*)(g_Wlo + (size_t)(n0 + row) * NN + c * 8);
    }
    for (int i = tid; i < 64 * 16; i += THREADS)
        ((float*)(smem + OFF_MEM))[i] = 0.0f;
    // nibble -> (a_low, a_high) bf16x2 LUT; entries hit distinct bank pairs
    if (tid < 16) {
        uint2 e;
        e.x = ((tid & 1) ? 0x00003F80u : 0u) | ((tid & 2) ? 0x3F800000u : 0u);
        e.y = ((tid & 4) ? 0x00003F80u : 0u) | ((tid & 8) ? 0x3F800000u : 0u);
        ((uint2*)(smem + OFF_LUT))[tid] = e;
    }
    __syncthreads();

    // per-thread constants
    const int rowq = lane >> 2;           // 0..7
    const int q4 = (lane & 3) * 4;        // nibble shift within a 16-bit half
    uint32_t ldsm_off;
    {
        int grp = lane >> 3;
        int row = ((grp >> 1) << 3) + (lane & 7);
        int koff = (grp & 1) * 8;
        ldsm_off = row * PITCHB + koff * 2;
    }
    const int eb = tid >> 2;              // epilogue batch row 0..63
    const int eq = (tid & 3) * 4;         // epilogue col base 0..12
    const int wsel = n0 >> 5;
    const int hsh = ((n0 >> 4) & 1) * 16; // half shift in the staged u32 word

    // permuted bit positions for the 4 epilogue neurons
    int npos[4];
    uint32_t pmask[4];
    #pragma unroll
    for (int i = 0; i < 4; ++i) {
        int c = eq + i;
        npos[i] = ((c & 7) >> 1) * 4 + (c & 1) + 2 * ((c >> 3) & 1);
        pmask[i] = 1u << (hsh + npos[i]);
    }

    uint32_t* const spkS = (uint32_t*)(smem + OFF_SPK);
    float* const memS = (float*)(smem + OFF_MEM);
    float* const redS = (float*)(smem + OFF_RED);
    const uint2* const lutS = (const uint2*)(smem + OFF_LUT);

    for (int t = 0; t < TT; ++t) {
        const uint32_t* gsrc = (t & 1) ? g_spk1 : g_spk0;
        uint32_t* gdst = (t & 1) ? g_spk0 : g_spk1;

        // ---- prefetch x for this step ----
        float4 xv = __ldg((const float4*)(x + ((size_t)eb * TT + t) * NN + n0 + eq));

        // ---- stage packed spikes [64 x 64 u32] -> padded SMEM rows ----
        {
            const uint4* src = (const uint4*)gsrc;
            #pragma unroll
            for (int i = tid; i < 1024; i += THREADS) {
                int row = i >> 4, c4 = i & 15;
                uint4 v = __ldcg(src + i);
                *(uint4*)(smem + OFF_SPK + (row * SPK_STRIDE + c4 * 4) * 4) = v;
            }
        }
        __syncthreads();

        // ---- GEMM: warp owns a k-eighth, all 4 m-tiles; A via nibble LUT ----
        float acc[4][2][4];
        #pragma unroll
        for (int m = 0; m < 4; ++m)
            #pragma unroll
            for (int nh = 0; nh < 2; ++nh)
                #pragma unroll
                for (int e = 0; e < 4; ++e) acc[m][nh][e] = 0.0f;

        #pragma unroll 2
        for (int j = 0; j < 8; ++j) {
            const int widx = (wid << 3) + j;          // u32 spike word index
            uint32_t bh[2][4], bl[2][4];
            #pragma unroll
            for (int h = 0; h < 2; ++h) {
                const int kt = widx * 2 + h;
                ldsm4(bh[h], sbase + OFF_WHI + ldsm_off + kt * 32);
                ldsm4(bl[h], sbase + OFF_WLO + ldsm_off + kt * 32);
            }
            #pragma unroll
            for (int m = 0; m < 4; ++m) {
                const uint32_t w0 = spkS[(m * 16 + rowq) * SPK_STRIDE + widx];
                const uint32_t w1 = spkS[(m * 16 + rowq + 8) * SPK_STRIDE + widx];
                #pragma unroll
                for (int h = 0; h < 2; ++h) {
                    uint2 u0 = lutS[(w0 >> (h * 16 + q4)) & 0xFu];
                    uint2 u1 = lutS[(w1 >> (h * 16 + q4)) & 0xFu];
                    uint32_t a[4] = {u0.x, u1.x, u0.y, u1.y};
                    mma_bf16(acc[m][0], a, bh[h][0], bh[h][1]);
                    mma_bf16(acc[m][1], a, bh[h][2], bh[h][3]);
                    mma_bf16(acc[m][0], a, bl[h][0], bl[h][1]);
                    mma_bf16(acc[m][1], a, bl[h][2], bl[h][3]);
                }
            }
        }

        // ---- dump per-warp partials ----
        {
            float* pw = redS + wid * 1024;
            const int c0 = (lane & 3) * 2;
            #pragma unroll
            for (int m = 0; m < 4; ++m)
                #pragma unroll
                for (int nh = 0; nh < 2; ++nh) {
                    const int col = nh * 8 + c0;
                    const int r = m * 16 + rowq;
                    *(float2*)(pw + r * 16 + col) = make_float2(acc[m][nh][0], acc[m][nh][1]);
                    *(float2*)(pw + (r + 8) * 16 + col) = make_float2(acc[m][nh][2], acc[m][nh][3]);
                }
        }
        __syncthreads();

        // ---- reduce 8 partials + LIF epilogue (4 outputs per thread) ----
        float4 s = *(float4*)(redS + eb * 16 + eq);
        #pragma unroll
        for (int w = 1; w < 8; ++w) {
            float4 p = *(float4*)(redS + w * 1024 + eb * 16 + eq);
            s.x += p.x; s.y += p.y; s.z += p.z; s.w += p.w;
        }

        float4 mv = *(float4*)(memS + eb * 16 + eq);
        const uint32_t pw = spkS[eb * SPK_STRIDE + wsel];

        float cur0 = xv.x + s.x, cur1 = xv.y + s.y;
        float cur2 = xv.z + s.z, cur3 = xv.w + s.w;
        float m0 = (pw & pmask[0]) ? cur0 : fmaf(0.96f, mv.x, cur0);
        float m1 = (pw & pmask[1]) ? cur1 : fmaf(0.96f, mv.y, cur1);
        float m2 = (pw & pmask[2]) ? cur2 : fmaf(0.96f, mv.z, cur2);
        float m3 = (pw & pmask[3]) ? cur3 : fmaf(0.96f, mv.w, cur3);

        unsigned s0 = (m0 >= 0.5f), s1 = (m1 >= 0.5f);
        unsigned s2 = (m2 >= 0.5f), s3 = (m3 >= 0.5f);

        *(float4*)(memS + eb * 16 + eq) = make_float4(m0, m1, m2, m3);

        // pack new spike bits (permuted positions) -> u16 per (batch row, CTA)
        unsigned v = (s0 << npos[0]) | (s1 << npos[1]) | (s2 << npos[2]) | (s3 << npos[3]);
        v |= __shfl_xor_sync(0xFFFFFFFFu, v, 1);
        v |= __shfl_xor_sync(0xFFFFFFFFu, v, 2);
        if ((tid & 3) == 0)
            ((uint16_t*)gdst)[eb * 128 + blockIdx.x] = (uint16_t)v;

        // ---- barrier arrive, overlap out-store with wait ----
        __syncthreads();
        if (tid == 0)
            asm volatile("red.release.gpu.global.add.u32 [%0], 1;" :: "l"(&g_bar) : "memory");

        *(float4*)(out + ((size_t)eb * TT + t) * NN + n0 + eq) =
            make_float4((float)s0, (float)s1, (float)s2, (float)s3);

        if (tid == 0) {
            const unsigned tgt = (unsigned)(CTAS * (t + 1));
            unsigned bv;
            do {
                asm volatile("ld.acquire.gpu.global.u32 %0, [%1];" : "=r"(bv) : "l"(&g_bar) : "memory");
            } while (bv < tgt);
        }
        __syncthreads();
    }
}

// ---- launch ----
extern "C" void kernel_launch(void* const* d_in, const int* in_sizes, int n_in,
                              void* d_out, int out_size) {
    const float* x = (const float*)d_in[0];
    const float* rec = (const float*)d_in[1];
    if (n_in >= 2 && in_sizes[0] == NN * NN) {
        x = (const float*)d_in[1];
        rec = (const float*)d_in[0];
    }
    float* out = (float*)d_out;

    cudaFuncSetAttribute(rsnn_kernel, cudaFuncAttributeMaxDynamicSharedMemorySize, SMEM_TOTAL);

    dim3 cg(NN / 32, NN / 32), cb(32, 32);
    prep_kernel<<<cg, cb>>>(rec);
    rsnn_kernel<<<CTAS, THREADS, SMEM_TOTAL>>>(x, out);
}